// round 3
// baseline (speedup 1.0000x reference)
#include <cuda_runtime.h>
#include <math.h>

#define N_   512
#define M_   2048
#define C_   256
#define KTOP 6

typedef unsigned long long ull;

// Scratch (static __device__ globals: allocation-free per harness rules)
__device__ float g_anti[2][N_ * M_];   // split-K partials
__device__ float g_rowco[N_];
__device__ int   g_cnt = 0;

// ---- packed f32x2 helpers (FFMA2: 2 FMA per instruction on sm_103a) -------
__device__ __forceinline__ ull pack2(float x) {
    ull r; asm("mov.b64 %0, {%1, %1};" : "=l"(r) : "f"(x)); return r;
}
__device__ __forceinline__ void fma2(ull& d, ull a, ull b) {
    asm("fma.rn.f32x2 %0, %1, %2, %0;" : "+l"(d) : "l"(a), "l"(b));
}
__device__ __forceinline__ void unpack2(ull v, float& lo, float& hi) {
    asm("mov.b64 {%0, %1}, %2;" : "=f"(lo), "=f"(hi) : "l"(v));
}

// ---------------------------------------------------------------------------
// Kernel 1: partial_z[n,m] = Aq_z[m] - 2 * dot_z(w'*micro[n], micro_all[m])
//   w'[c] = fc_w[c] - 1/C ; Aq_z over this block's K-half.
//   (per-row Bq[n] term dropped: row-constant, invariant for top-k + exp
//    weights; full anti = partial_0 + partial_1, summed in topk.)
// Tile 128(m) x 128(n) x Khalf(128), 256 threads, 8x8 frag, TK=16, double-buf.
// grid (16, 4, 2) = 128 blocks x 8 warps -> 2 warps per SMSP for latency hiding.
// ---------------------------------------------------------------------------
#define TMm 128
#define TNn 128
#define TK  16
#define KHALF 128

__global__ void __launch_bounds__(256, 1)
anti_gemm(const float* __restrict__ micro,
          const float* __restrict__ micro_all,
          const float* __restrict__ fc_w) {
    __shared__ float As[2][TK][TNn + 4];     // As[k][n] = w'[k]*micro[n,k]
    __shared__ float Bs[2][TK][TMm + 4];     // Bs[k][m] = micro_all[m,k]
    __shared__ float sw[C_];                 // w'
    __shared__ float sAqP[TMm * 4];          // Aq partials [m_local*4 + kgrp]

    const int tid = threadIdx.x;
    const int m0 = blockIdx.x * TMm;
    const int n0 = blockIdx.y * TNn;
    const int z  = blockIdx.z;
    const int kb = z * KHALF;

    sw[tid] = fc_w[tid] - (1.0f / (float)C_);
    __syncthreads();

    const int lr  = tid >> 2;           // 0..63 loader row slot
    const int lkp = (tid & 3) << 2;     // k sub-offset 0,4,8,12
    const int tx  = tid & 15;           // m frag group (8 cols each)
    const int ty  = tid >> 4;           // n frag group (8 rows each)

    float4 pb[2], pa[2];
    float  aqp[2] = {0.f, 0.f};
    ull    acc[8][4];
    #pragma unroll
    for (int i = 0; i < 8; i++)
        #pragma unroll
        for (int j = 0; j < 4; j++) acc[i][j] = 0ull;

    auto LOAD = [&](int k0) {           // k0 is global k
        #pragma unroll
        for (int i = 0; i < 2; i++)
            pb[i] = *(const float4*)&micro_all[(m0 + lr + 64 * i) * C_ + k0 + lkp];
        #pragma unroll
        for (int i = 0; i < 2; i++)
            pa[i] = *(const float4*)&micro[(n0 + lr + 64 * i) * C_ + k0 + lkp];
    };
    auto STORE = [&](int buf, int k0) {
        float4 w4 = *(const float4*)&sw[k0 + lkp];
        #pragma unroll
        for (int i = 0; i < 2; i++) {
            int r = lr + 64 * i;
            Bs[buf][lkp + 0][r] = pb[i].x;
            Bs[buf][lkp + 1][r] = pb[i].y;
            Bs[buf][lkp + 2][r] = pb[i].z;
            Bs[buf][lkp + 3][r] = pb[i].w;
            aqp[i] += w4.x * pb[i].x * pb[i].x + w4.y * pb[i].y * pb[i].y
                    + w4.z * pb[i].z * pb[i].z + w4.w * pb[i].w * pb[i].w;
        }
        #pragma unroll
        for (int i = 0; i < 2; i++) {
            int r = lr + 64 * i;
            As[buf][lkp + 0][r] = w4.x * pa[i].x;
            As[buf][lkp + 1][r] = w4.y * pa[i].y;
            As[buf][lkp + 2][r] = w4.z * pa[i].z;
            As[buf][lkp + 3][r] = w4.w * pa[i].w;
        }
    };

    LOAD(kb);
    STORE(0, kb);
    __syncthreads();

    #pragma unroll 1
    for (int c = 0; c < KHALF / TK; c++) {
        if (c < KHALF / TK - 1) LOAD(kb + (c + 1) * TK);
        const int buf = c & 1;
        #pragma unroll
        for (int k = 0; k < TK; k++) {
            float4 a0 = *(const float4*)&As[buf][k][ty * 8];
            float4 a1 = *(const float4*)&As[buf][k][ty * 8 + 4];
            ulonglong2 b0 = *(const ulonglong2*)&Bs[buf][k][tx * 8];
            ulonglong2 b1 = *(const ulonglong2*)&Bs[buf][k][tx * 8 + 4];
            ull bb0 = b0.x, bb1 = b0.y, bb2 = b1.x, bb3 = b1.y;
            float av[8] = {a0.x, a0.y, a0.z, a0.w, a1.x, a1.y, a1.z, a1.w};
            #pragma unroll
            for (int i = 0; i < 8; i++) {
                ull aa = pack2(av[i]);
                fma2(acc[i][0], aa, bb0);
                fma2(acc[i][1], aa, bb1);
                fma2(acc[i][2], aa, bb2);
                fma2(acc[i][3], aa, bb3);
            }
        }
        if (c < KHALF / TK - 1) {
            STORE((c + 1) & 1, kb + (c + 1) * TK);
            __syncthreads();
        }
    }

    // publish Aq partials: slot (row*4 + kgrp) == tid + 256*i by construction
    sAqP[tid]       = aqp[0];
    sAqP[tid + 256] = aqp[1];
    __syncthreads();

    float aqv[8];
    #pragma unroll
    for (int t = 0; t < 8; t++) {
        float4 q = *(const float4*)&sAqP[(tx * 8 + t) * 4];
        aqv[t] = (q.x + q.y) + (q.z + q.w);
    }

    float* base = &g_anti[z][0];
    #pragma unroll
    for (int i = 0; i < 8; i++) {
        int n = n0 + ty * 8 + i;
        float lo0, hi0, lo1, hi1;
        unpack2(acc[i][0], lo0, hi0);
        unpack2(acc[i][1], lo1, hi1);
        float4 o0 = make_float4(aqv[0] - 2.f * lo0, aqv[1] - 2.f * hi0,
                                aqv[2] - 2.f * lo1, aqv[3] - 2.f * hi1);
        unpack2(acc[i][2], lo0, hi0);
        unpack2(acc[i][3], lo1, hi1);
        float4 o1 = make_float4(aqv[4] - 2.f * lo0, aqv[5] - 2.f * hi0,
                                aqv[6] - 2.f * lo1, aqv[7] - 2.f * hi1);
        float* dst = &base[n * M_ + m0 + tx * 8];
        *(float4*)&dst[0] = o0;
        *(float4*)&dst[4] = o1;
    }
}

// ---------------------------------------------------------------------------
// Kernel 2: warp-per-row top-6 (lax.top_k semantics), renormalized exp
// weights over the 6, output row, co partial + deterministic last-block sum.
// grid 128 x 128 threads (4 warps/block). Scan uses 8 independent chains of 8
// to break the serial dependency (ILP-8), tie-break exact (lowest index).
// ---------------------------------------------------------------------------
__global__ void __launch_bounds__(128)
topk_kernel(const float* __restrict__ micro,
            const float* __restrict__ micro_all,
            const float* __restrict__ label,
            const float* __restrict__ label_all,
            float* __restrict__ out, int out_size) {
    const int lane = threadIdx.x & 31;
    const int warp = threadIdx.x >> 5;
    const int n = blockIdx.x * 4 + warp;

    // v[j] <-> global column j*32 + lane ; anti = partial0 + partial1
    const float* r0 = &g_anti[0][n * M_];
    const float* r1 = &g_anti[1][n * M_];
    float v[M_ / 32];
    #pragma unroll
    for (int j = 0; j < M_ / 32; j++)
        v[j] = r0[j * 32 + lane] + r1[j * 32 + lane];

    float selv[KTOP];
    int   seli[KTOP];
    #pragma unroll
    for (int it = 0; it < KTOP; it++) {
        // 8 independent chains over contiguous j-ranges (index-ascending)
        float cb[8]; int cbi[8];
        #pragma unroll
        for (int c = 0; c < 8; c++) { cb[c] = v[8 * c]; cbi[c] = (8 * c) * 32 + lane; }
        #pragma unroll
        for (int t = 1; t < 8; t++)
            #pragma unroll
            for (int c = 0; c < 8; c++) {
                int j = 8 * c + t;
                if (v[j] > cb[c]) { cb[c] = v[j]; cbi[c] = j * 32 + lane; }
            }
        float best = cb[0]; int bi = cbi[0];
        #pragma unroll
        for (int c = 1; c < 8; c++)       // ascending c: strict > keeps lowest idx
            if (cb[c] > best) { best = cb[c]; bi = cbi[c]; }
        #pragma unroll
        for (int s = 16; s; s >>= 1) {
            float ov = __shfl_xor_sync(0xffffffffu, best, s);
            int   oi = __shfl_xor_sync(0xffffffffu, bi, s);
            if (ov > best || (ov == best && oi < bi)) { best = ov; bi = oi; }
        }
        selv[it] = best;
        seli[it] = bi;
        if ((bi & 31) == lane) {          // owner removes the winner
            int jj = bi >> 5;
            #pragma unroll
            for (int j = 0; j < M_ / 32; j++)
                if (j == jj) v[j] = -INFINITY;
        }
    }

    float e[KTOP], s = 0.f;
    #pragma unroll
    for (int k = 0; k < KTOP; k++) { e[k] = expf(selv[k] - selv[0]); s += e[k]; }
    const float inv = 1.f / s;

    if (lane == 0) {
        float lab = label[n];
        float co = 0.f;
        #pragma unroll
        for (int k = 0; k < KTOP; k++)
            co += (e[k] * inv) * fabsf(label_all[seli[k]] - lab);
        g_rowco[n] = co;
    }

    // micro_tmp[n,:] = micro[n,:] + sum_k cut_k * micro_all[idx_k,:]
    const float* mi = &micro[n * C_];
    float* op = &out[n * C_];
    #pragma unroll
    for (int jj = 0; jj < C_ / 32; jj++) {
        int c = lane + jj * 32;
        float o = mi[c];
        #pragma unroll
        for (int k = 0; k < KTOP; k++)
            o += (e[k] * inv) * micro_all[seli[k] * C_ + c];
        op[c] = o;
    }

    // deterministic co_loss: last arriving block does a fixed-order tree
    __threadfence();
    __syncthreads();
    __shared__ int isLast;
    if (threadIdx.x == 0)
        isLast = (atomicAdd(&g_cnt, 1) == (int)gridDim.x - 1);
    __syncthreads();
    if (isLast) {
        __shared__ float red[128];
        int t = threadIdx.x;
        red[t] = (g_rowco[t] + g_rowco[t + 128])
               + (g_rowco[t + 256] + g_rowco[t + 384]);
        __syncthreads();
        #pragma unroll
        for (int s2 = 64; s2 > 0; s2 >>= 1) {
            if (t < s2) red[t] += red[t + s2];
            __syncthreads();
        }
        if (t == 0) {
            if (out_size > N_ * C_)
                out[N_ * C_] = 1e-4f + red[0] / (float)N_;
            g_cnt = 0;   // reset for graph replays
        }
    }
}

// ---------------------------------------------------------------------------
extern "C" void kernel_launch(void* const* d_in, const int* in_sizes, int n_in,
                              void* d_out, int out_size) {
    const float* micro     = (const float*)d_in[0];   // [512, 256]
    const float* label     = (const float*)d_in[1];   // [512]
    const float* micro_all = (const float*)d_in[2];   // [2048, 256]
    const float* label_all = (const float*)d_in[3];   // [2048]
    const float* fc_w      = (const float*)d_in[4];   // [256]
    float* out = (float*)d_out;

    anti_gemm<<<dim3(M_ / TMm, N_ / TNn, 2), 256>>>(micro, micro_all, fc_w);
    topk_kernel<<<N_ / 4, 128>>>(micro, micro_all, label, label_all, out, out_size);
}

// round 8
// speedup vs baseline: 1.0779x; 1.0779x over previous
#include <cuda_runtime.h>
#include <math.h>

#define N_   512
#define M_   2048
#define C_   256
#define KTOP 6

typedef unsigned long long ull;

// Scratch (static __device__ globals: allocation-free per harness rules)
__device__ float g_anti[2][N_ * M_];   // split-K partials
__device__ float g_rowco[N_];
__device__ int   g_cnt = 0;

// ---- packed f32x2 helpers (FFMA2: 2 FMA per instruction on sm_103a) -------
__device__ __forceinline__ ull pack2(float x) {
    ull r; asm("mov.b64 %0, {%1, %1};" : "=l"(r) : "f"(x)); return r;
}
__device__ __forceinline__ void fma2(ull& d, ull a, ull b) {
    asm("fma.rn.f32x2 %0, %1, %2, %0;" : "+l"(d) : "l"(a), "l"(b));
}
__device__ __forceinline__ void unpack2(ull v, float& lo, float& hi) {
    asm("mov.b64 {%0, %1}, %2;" : "=f"(lo), "=f"(hi) : "l"(v));
}

// ---------------------------------------------------------------------------
// Kernel 1: partial_z[n,m] = Aq_z[m] - 2 * dot_z(w'*micro[n], micro_all[m])
//   w'[c] = fc_w[c] - 1/C ; Aq_z over this block's K-half.
//   (per-row Bq[n] dropped: row-constant -> invariant for top-k + exp weights)
// Tile 128(m) x 64(n) x Khalf(128), 128 threads, 8x8 frag, TK=16, double-buf.
// grid (16, 8, 2) = 256 blocks -> 2 CTAs/SM: cross-CTA latency hiding.
// ---------------------------------------------------------------------------
#define TMm 128
#define TNn 64
#define TK  16
#define KHALF 128

__global__ void __launch_bounds__(128, 2)
anti_gemm(const float* __restrict__ micro,
          const float* __restrict__ micro_all,
          const float* __restrict__ fc_w) {
    __shared__ float As[2][TK][TNn + 4];     // As[k][n] = w'[k]*micro[n,k]
    __shared__ float Bs[2][TK][TMm + 4];     // Bs[k][m] = micro_all[m,k]
    __shared__ float sw[C_];                 // w'
    __shared__ float sAqP[TMm * 4];          // Aq partials [m_local*4 + kgrp]

    const int tid = threadIdx.x;
    const int m0 = blockIdx.x * TMm;
    const int n0 = blockIdx.y * TNn;
    const int z  = blockIdx.z;
    const int kb = z * KHALF;

    sw[tid]       = fc_w[tid]       - (1.0f / (float)C_);
    sw[tid + 128] = fc_w[tid + 128] - (1.0f / (float)C_);
    __syncthreads();

    const int lr  = tid >> 2;           // 0..31 loader row slot
    const int lkp = (tid & 3) << 2;     // k sub-offset 0,4,8,12
    const int tx  = tid & 15;           // m frag group (8 cols)
    const int ty  = tid >> 4;           // n frag group (8 rows), 0..7

    float4 pb[4], pa[2];
    float  aqp[4] = {0.f, 0.f, 0.f, 0.f};
    ull    acc[8][4];
    #pragma unroll
    for (int i = 0; i < 8; i++)
        #pragma unroll
        for (int j = 0; j < 4; j++) acc[i][j] = 0ull;

    auto LOAD = [&](int k0) {           // k0 global
        #pragma unroll
        for (int i = 0; i < 4; i++)
            pb[i] = *(const float4*)&micro_all[(m0 + lr + 32 * i) * C_ + k0 + lkp];
        #pragma unroll
        for (int i = 0; i < 2; i++)
            pa[i] = *(const float4*)&micro[(n0 + lr + 32 * i) * C_ + k0 + lkp];
    };
    auto STORE = [&](int buf, int k0) {
        float4 w4 = *(const float4*)&sw[k0 + lkp];
        #pragma unroll
        for (int i = 0; i < 4; i++) {
            int r = lr + 32 * i;
            Bs[buf][lkp + 0][r] = pb[i].x;
            Bs[buf][lkp + 1][r] = pb[i].y;
            Bs[buf][lkp + 2][r] = pb[i].z;
            Bs[buf][lkp + 3][r] = pb[i].w;
            aqp[i] += w4.x * pb[i].x * pb[i].x + w4.y * pb[i].y * pb[i].y
                    + w4.z * pb[i].z * pb[i].z + w4.w * pb[i].w * pb[i].w;
        }
        #pragma unroll
        for (int i = 0; i < 2; i++) {
            int r = lr + 32 * i;
            As[buf][lkp + 0][r] = w4.x * pa[i].x;
            As[buf][lkp + 1][r] = w4.y * pa[i].y;
            As[buf][lkp + 2][r] = w4.z * pa[i].z;
            As[buf][lkp + 3][r] = w4.w * pa[i].w;
        }
    };

    LOAD(kb);
    STORE(0, kb);
    __syncthreads();

    #pragma unroll 1
    for (int c = 0; c < KHALF / TK; c++) {
        if (c < KHALF / TK - 1) LOAD(kb + (c + 1) * TK);
        const int buf = c & 1;
        #pragma unroll
        for (int k = 0; k < TK; k++) {
            float4 a0 = *(const float4*)&As[buf][k][ty * 8];
            float4 a1 = *(const float4*)&As[buf][k][ty * 8 + 4];
            ulonglong2 b0 = *(const ulonglong2*)&Bs[buf][k][tx * 8];
            ulonglong2 b1 = *(const ulonglong2*)&Bs[buf][k][tx * 8 + 4];
            ull bb0 = b0.x, bb1 = b0.y, bb2 = b1.x, bb3 = b1.y;
            float av[8] = {a0.x, a0.y, a0.z, a0.w, a1.x, a1.y, a1.z, a1.w};
            #pragma unroll
            for (int i = 0; i < 8; i++) {
                ull aa = pack2(av[i]);
                fma2(acc[i][0], aa, bb0);
                fma2(acc[i][1], aa, bb1);
                fma2(acc[i][2], aa, bb2);
                fma2(acc[i][3], aa, bb3);
            }
        }
        if (c < KHALF / TK - 1) {
            STORE((c + 1) & 1, kb + (c + 1) * TK);
            __syncthreads();
        }
    }

    // Aq partials: slot (m_local*4 + kgrp) == tid + 128*i by construction
    #pragma unroll
    for (int i = 0; i < 4; i++) sAqP[tid + 128 * i] = aqp[i];
    __syncthreads();

    float aqv[8];
    #pragma unroll
    for (int t = 0; t < 8; t++) {
        float4 q = *(const float4*)&sAqP[(tx * 8 + t) * 4];
        aqv[t] = (q.x + q.y) + (q.z + q.w);
    }

    float* base = &g_anti[z][0];
    #pragma unroll
    for (int i = 0; i < 8; i++) {
        int n = n0 + ty * 8 + i;
        float lo0, hi0, lo1, hi1;
        unpack2(acc[i][0], lo0, hi0);
        unpack2(acc[i][1], lo1, hi1);
        float4 o0 = make_float4(aqv[0] - 2.f * lo0, aqv[1] - 2.f * hi0,
                                aqv[2] - 2.f * lo1, aqv[3] - 2.f * hi1);
        unpack2(acc[i][2], lo0, hi0);
        unpack2(acc[i][3], lo1, hi1);
        float4 o1 = make_float4(aqv[4] - 2.f * lo0, aqv[5] - 2.f * hi0,
                                aqv[6] - 2.f * lo1, aqv[7] - 2.f * hi1);
        float* dst = &base[n * M_ + m0 + tx * 8];
        *(float4*)&dst[0] = o0;
        *(float4*)&dst[4] = o1;
    }
}

// ---------------------------------------------------------------------------
// Kernel 2: one block (4 warps) per row. Each warp finds top-6 of its 512-col
// segment (exact lax.top_k tie-break), warp 0 merges the 24 candidates,
// weights + output row + co partial, last-block deterministic co_loss.
// grid 512 x 128 threads -> ~14 warps/SM: memory latency hidden.
// ---------------------------------------------------------------------------
__global__ void __launch_bounds__(128)
topk_kernel(const float* __restrict__ micro,
            const float* __restrict__ micro_all,
            const float* __restrict__ label,
            const float* __restrict__ label_all,
            float* __restrict__ out, int out_size) {
    const int tid  = threadIdx.x;
    const int lane = tid & 31;
    const int w    = tid >> 5;
    const int n    = blockIdx.x;
    const int base = w * 512;

    const float* r0 = &g_anti[0][n * M_];
    const float* r1 = &g_anti[1][n * M_];
    float v[16];
    #pragma unroll
    for (int j = 0; j < 16; j++) {
        int c = base + j * 32 + lane;
        v[j] = r0[c] + r1[c];
    }

    __shared__ float sv[4 * KTOP];
    __shared__ int   si[4 * KTOP];
    __shared__ float wgt[KTOP];
    __shared__ int   gidx[KTOP];

    float selv[KTOP];
    int   seli[KTOP];
    #pragma unroll
    for (int it = 0; it < KTOP; it++) {
        // 4 independent chains of 4 (index-ascending within and across chains)
        float cb[4]; int cbi[4];
        #pragma unroll
        for (int c = 0; c < 4; c++) { cb[c] = v[4 * c]; cbi[c] = base + (4 * c) * 32 + lane; }
        #pragma unroll
        for (int t = 1; t < 4; t++)
            #pragma unroll
            for (int c = 0; c < 4; c++) {
                int j = 4 * c + t;
                if (v[j] > cb[c]) { cb[c] = v[j]; cbi[c] = base + j * 32 + lane; }
            }
        float best = cb[0]; int bi = cbi[0];
        #pragma unroll
        for (int c = 1; c < 4; c++)
            if (cb[c] > best) { best = cb[c]; bi = cbi[c]; }
        #pragma unroll
        for (int s = 16; s; s >>= 1) {
            float ov = __shfl_xor_sync(0xffffffffu, best, s);
            int   oi = __shfl_xor_sync(0xffffffffu, bi, s);
            if (ov > best || (ov == best && oi < bi)) { best = ov; bi = oi; }
        }
        selv[it] = best; seli[it] = bi;
        int rel = bi - base;
        if ((rel & 31) == lane) {          // owner removes the winner
            int jj = rel >> 5;
            #pragma unroll
            for (int j = 0; j < 16; j++)
                if (j == jj) v[j] = -INFINITY;
        }
    }
    if (lane == 0) {
        #pragma unroll
        for (int k = 0; k < KTOP; k++) { sv[w * KTOP + k] = selv[k]; si[w * KTOP + k] = seli[k]; }
    }
    __syncthreads();

    if (w == 0) {
        // merge 24 candidates (indices unique across candidates)
        float mv = (lane < 4 * KTOP) ? sv[lane] : -INFINITY;
        int   mi = (lane < 4 * KTOP) ? si[lane] : 0x7fffffff;
        float fv[KTOP]; int fi[KTOP];
        #pragma unroll
        for (int it = 0; it < KTOP; it++) {
            float best = mv; int bi = mi;
            #pragma unroll
            for (int s = 16; s; s >>= 1) {
                float ov = __shfl_xor_sync(0xffffffffu, best, s);
                int   oi = __shfl_xor_sync(0xffffffffu, bi, s);
                if (ov > best || (ov == best && oi < bi)) { best = ov; bi = oi; }
            }
            fv[it] = best; fi[it] = bi;
            if (mi == bi) mv = -INFINITY;
        }
        float e[KTOP], s = 0.f;
        #pragma unroll
        for (int k = 0; k < KTOP; k++) { e[k] = expf(fv[k] - fv[0]); s += e[k]; }
        const float inv = 1.f / s;
        if (lane == 0) {
            float lab = label[n];
            float co = 0.f;
            #pragma unroll
            for (int k = 0; k < KTOP; k++) {
                float ck = e[k] * inv;
                wgt[k] = ck; gidx[k] = fi[k];
                co += ck * fabsf(label_all[fi[k]] - lab);
            }
            g_rowco[n] = co;
        }
    }
    __syncthreads();

    // micro_tmp[n,:] = micro[n,:] + sum_k cut_k * micro_all[idx_k,:]
    #pragma unroll
    for (int jj = 0; jj < C_ / 128; jj++) {
        int c = tid + 128 * jj;
        float o = micro[n * C_ + c];
        #pragma unroll
        for (int k = 0; k < KTOP; k++)
            o += wgt[k] * micro_all[gidx[k] * C_ + c];
        out[n * C_ + c] = o;
    }

    // deterministic co_loss: last arriving block does a fixed-order tree
    __threadfence();
    __syncthreads();
    __shared__ int isLast;
    if (tid == 0)
        isLast = (atomicAdd(&g_cnt, 1) == (int)gridDim.x - 1);
    __syncthreads();
    if (isLast) {
        __shared__ float red[128];
        red[tid] = (g_rowco[tid] + g_rowco[tid + 128])
                 + (g_rowco[tid + 256] + g_rowco[tid + 384]);
        __syncthreads();
        #pragma unroll
        for (int s2 = 64; s2 > 0; s2 >>= 1) {
            if (tid < s2) red[tid] += red[tid + s2];
            __syncthreads();
        }
        if (tid == 0) {
            if (out_size > N_ * C_)
                out[N_ * C_] = 1e-4f + red[0] / (float)N_;
            g_cnt = 0;   // reset for graph replays
        }
    }
}

// ---------------------------------------------------------------------------
extern "C" void kernel_launch(void* const* d_in, const int* in_sizes, int n_in,
                              void* d_out, int out_size) {
    const float* micro     = (const float*)d_in[0];   // [512, 256]
    const float* label     = (const float*)d_in[1];   // [512]
    const float* micro_all = (const float*)d_in[2];   // [2048, 256]
    const float* label_all = (const float*)d_in[3];   // [2048]
    const float* fc_w      = (const float*)d_in[4];   // [256]
    float* out = (float*)d_out;

    anti_gemm<<<dim3(M_ / TMm, N_ / TNn, 2), 128>>>(micro, micro_all, fc_w);
    topk_kernel<<<N_, 128>>>(micro, micro_all, label, label_all, out, out_size);
}